// round 6
// baseline (speedup 1.0000x reference)
#include <cuda_runtime.h>
#include <math.h>

#define BB   8
#define NA   4096
#define NAA  1024
#define NPC  4096
#define KNB  16
#define KNC  14
#define GG   32
#define DA   12
#define FF   128
#define DD   128
#define NATTR 39     // NCAT+1
#define APB  8       // atoms per block in atom_kernel
#define GP   33      // padded inner dim of sh_g (bank spread)

// -------- scratch (static device globals; no allocation allowed) ----------
__device__ float g_att   [BB*NA*DD];    // 16 MB
__device__ float g_feat  [BB*NA*DD];    // 16 MB
__device__ float g_masky [BB*NA];       // 128 KB
__device__ float g_pooled[BB*NAA*DD];   // 4 MB
__device__ float g_mean  [DD];
__device__ float g_invstd[DD];

// -------- packed f32x2 helpers (SASS FFMA2 path) --------------------------
__device__ __forceinline__ unsigned long long pk2(float lo, float hi) {
    unsigned long long r;
    asm("mov.b64 %0, {%1, %2};" : "=l"(r) : "f"(lo), "f"(hi));
    return r;
}
__device__ __forceinline__ void fma2(unsigned long long& d,
                                     unsigned long long a,
                                     unsigned long long b) {
    asm("fma.rn.f32x2 %0, %1, %2, %0;" : "+l"(d) : "l"(a), "l"(b));
}
__device__ __forceinline__ float2 upk2(unsigned long long v) {
    float2 f;
    asm("mov.b64 {%0, %1}, %2;" : "=f"(f.x), "=f"(f.y) : "l"(v));
    return f;
}

// shared layout: W tiles reuse the g/anb region (dead after stage 3)
struct __align__(16) SmemA {
    union __align__(16) U {
        struct { float g[APB][KNB][GP]; float anb[APB][KNB][DA]; } s23; // 19968 B
        float w4[32*FF];                                   // stage-4 W_nem tile
        struct { float wa[16*FF]; float wf[16*FF]; } s5;   // stage-5 tiles
    } u;
    float M   [APB][GG*DA];
    float y   [APB][FF];
    float attr[NATTR*DA];
    float mattr[NATTR];
    float gc  [GG*3];
    float R   [APB][9];
    float c   [APB][3];
    float masky[APB];
};

// ==========================================================================
// Kernel A: per-atom. 8 atoms per block, 128 threads.
// ==========================================================================
__global__ __launch_bounds__(128) void atom_kernel(
    const float* __restrict__ pc,         // (B,NPC,3)
    const float* __restrict__ mask_atom,  // (B,NA,1)
    const float* __restrict__ attr_table, // (39,12)
    const float* __restrict__ gauss,      // (32,3)
    const float* __restrict__ W_nem,      // (384,128)
    const float* __restrict__ W_att,      // (128,128)
    const float* __restrict__ W_feat,     // (128,128)
    const int*   __restrict__ frame_idx,  // (B,NA,3)
    const int*   __restrict__ attr_idx,   // (B,NA)
    const int*   __restrict__ nb_idx)     // (B,NA,16)
{
    __shared__ SmemA S;

    const int t  = threadIdx.x;
    const int ai = t >> 4;
    const int k  = t & 15;
    const long gaBase = (long)blockIdx.x * APB;
    const long ga = gaBase + ai;               // global atom id
    const int  b  = (int)(ga >> 12);           // NA = 4096

    // ---- stage 0: stage small tables in smem ----
    for (int i = t; i < NATTR*DA; i += 128) S.attr[i] = attr_table[i];
    for (int i = t; i < GG*3;     i += 128) S.gc[i]   = gauss[i];
    __syncthreads();

    // ---- stage 1: mattr per table row; frame R per atom ----
    if (t < NATTR) {
        float any = 0.f;
        #pragma unroll
        for (int a = 0; a < DA; a++) if (S.attr[t*DA + a] != 0.f) any = 1.f;
        S.mattr[t] = any;
    }
    if (k == 0) {
        const int* fi = frame_idx + ga*3;
        const float* pb = pc + (long)b*NPC*3;
        int i0 = fi[0], i1 = fi[1], i2 = fi[2];
        float c0 = pb[i1*3+0], c1 = pb[i1*3+1], c2 = pb[i1*3+2];
        float a0 = pb[i2*3+0]-c0, a1 = pb[i2*3+1]-c1, a2 = pb[i2*3+2]-c2;
        float n1 = sqrtf(a0*a0 + a1*a1 + a2*a2);
        float s1 = 1.f / (n1 + 1e-8f);
        float u10 = a0*s1, u11 = a1*s1, u12 = a2*s1;
        float v0 = pb[i0*3+0]-c0, v1 = pb[i0*3+1]-c1, v2 = pb[i0*3+2]-c2;
        float dp = v0*u10 + v1*u11 + v2*u12;
        float w0 = v0 - dp*u10, w1 = v1 - dp*u11, w2 = v2 - dp*u12;
        float n2 = sqrtf(w0*w0 + w1*w1 + w2*w2);
        float s2 = 1.f / (n2 + 1e-8f);
        float u20 = w0*s2, u21 = w1*s2, u22 = w2*s2;
        float u30 = u11*u22 - u12*u21;
        float u31 = u12*u20 - u10*u22;
        float u32 = u10*u21 - u11*u20;
        S.R[ai][0]=u10; S.R[ai][1]=u11; S.R[ai][2]=u12;
        S.R[ai][3]=u20; S.R[ai][4]=u21; S.R[ai][5]=u22;
        S.R[ai][6]=u30; S.R[ai][7]=u31; S.R[ai][8]=u32;
        S.c[ai][0]=c0;  S.c[ai][1]=c1;  S.c[ai][2]=c2;
    }
    __syncthreads();

    // ---- stage 2: per-(atom, neighbor): gaussian features + attr gather ----
    if (k == 0) {
        int own = attr_idx[ga];
        S.masky[ai] = mask_atom[ga] * S.mattr[own];
    }
    {
        int nb  = nb_idx[ga*KNB + k];             // [0, NA)
        long nbg = (long)b*NA + nb;
        int fi1 = frame_idx[nbg*3 + 1];
        const float* pb = pc + (long)b*NPC*3;
        float dx = pb[fi1*3+0] - S.c[ai][0];
        float dy = pb[fi1*3+1] - S.c[ai][1];
        float dz = pb[fi1*3+2] - S.c[ai][2];
        float r0 = S.R[ai][0]*dx + S.R[ai][1]*dy + S.R[ai][2]*dz;
        float r1 = S.R[ai][3]*dx + S.R[ai][4]*dy + S.R[ai][5]*dz;
        float r2 = S.R[ai][6]*dx + S.R[ai][7]*dy + S.R[ai][8]*dz;
        #pragma unroll
        for (int gi = 0; gi < GG; gi++) {
            float gx = r0 - S.gc[gi*3+0];
            float gy = r1 - S.gc[gi*3+1];
            float gz = r2 - S.gc[gi*3+2];
            S.u.s23.g[ai][k][gi] = __expf(-0.5f * (gx*gx + gy*gy + gz*gz));
        }
        int na = attr_idx[nbg];
        float m = S.mattr[na];
        #pragma unroll
        for (int a = 0; a < DA; a++)
            S.u.s23.anb[ai][k][a] = S.attr[na*DA + a] * m;
    }
    __syncthreads();

    // ---- stage 3: M[ai][gi][a] = sum_k g * a_nb  (born-packed FFMA2) ----
    for (int q = t; q < APB*GG*(DA/4); q += 128) {
        int a2 = q / (GG*(DA/4));
        int r  = q - a2*(GG*(DA/4));
        int gi = r / (DA/4);
        int aq = r - gi*(DA/4);
        unsigned long long acc01 = 0ull, acc23 = 0ull;
        const ulonglong2* anb2 = (const ulonglong2*)&S.u.s23.anb[a2][0][0];
        #pragma unroll
        for (int kk = 0; kk < KNB; kk++) {
            float gv = S.u.s23.g[a2][kk][gi];
            unsigned long long gg = pk2(gv, gv);
            ulonglong2 av = anb2[kk*(DA/4) + aq];
            fma2(acc01, av.x, gg);
            fma2(acc23, av.y, gg);
        }
        ulonglong2 res; res.x = acc01; res.y = acc23;
        ((ulonglong2*)&S.M[a2][0])[gi*(DA/4) + aq] = res;
    }

    // ---- stage 4: y[f] = (M . W_nem)/K * mask ----  thread t = f
    // W_nem staged through smem in 12 chunks of 32 rows, reg double-buffered.
    {
        unsigned long long acc2[APB];
        #pragma unroll
        for (int i = 0; i < APB; i++) acc2[i] = 0ull;

        const float4* Wn4 = (const float4*)W_nem;   // (384*128)/4 float4
        float4 pre[8];
        #pragma unroll
        for (int j = 0; j < 8; j++) pre[j] = Wn4[j*128 + t];   // chunk 0

        for (int c = 0; c < 12; c++) {
            __syncthreads();   // prev chunk consumed (c=0: stage-3 g/anb readers done)
            #pragma unroll
            for (int j = 0; j < 8; j++)
                ((float4*)S.u.w4)[j*128 + t] = pre[j];
            __syncthreads();
            if (c + 1 < 12) {
                #pragma unroll
                for (int j = 0; j < 8; j++)
                    pre[j] = Wn4[(c+1)*1024 + j*128 + t];
            }
            #pragma unroll
            for (int r4l = 0; r4l < 8; r4l++) {
                int rb = r4l*4;
                float w0 = S.u.w4[(rb+0)*FF + t];
                float w1 = S.u.w4[(rb+1)*FF + t];
                float w2 = S.u.w4[(rb+2)*FF + t];
                float w3 = S.u.w4[(rb+3)*FF + t];
                unsigned long long w01 = pk2(w0, w1);
                unsigned long long w23 = pk2(w2, w3);
                int r4 = c*8 + r4l;
                #pragma unroll
                for (int i = 0; i < APB; i++) {
                    ulonglong2 m2 = ((const ulonglong2*)&S.M[i][0])[r4];
                    fma2(acc2[i], m2.x, w01);
                    fma2(acc2[i], m2.y, w23);
                }
            }
        }
        __syncthreads();
        #pragma unroll
        for (int i = 0; i < APB; i++) {
            float2 f = upk2(acc2[i]);
            S.y[i][t] = (f.x + f.y) * (1.f/(float)KNB) * S.masky[i];
        }
    }

    // ---- stage 5: att/feat = y @ W ----  thread t = d
    // W_att+W_feat staged in 8 chunks of 16 rows each.
    {
        unsigned long long aA2[APB], aF2[APB];
        #pragma unroll
        for (int i = 0; i < APB; i++) { aA2[i] = 0ull; aF2[i] = 0ull; }

        const float4* Wa4 = (const float4*)W_att;    // (128*128)/4
        const float4* Wf4 = (const float4*)W_feat;
        float4 prea[4], pref[4];
        #pragma unroll
        for (int j = 0; j < 4; j++) {
            prea[j] = Wa4[j*128 + t];
            pref[j] = Wf4[j*128 + t];
        }

        for (int c = 0; c < 8; c++) {
            __syncthreads();   // prev chunk consumed; c=0: stage-4 w4 readers + y writers done
            #pragma unroll
            for (int j = 0; j < 4; j++) {
                ((float4*)S.u.s5.wa)[j*128 + t] = prea[j];
                ((float4*)S.u.s5.wf)[j*128 + t] = pref[j];
            }
            __syncthreads();
            if (c + 1 < 8) {
                #pragma unroll
                for (int j = 0; j < 4; j++) {
                    prea[j] = Wa4[(c+1)*512 + j*128 + t];
                    pref[j] = Wf4[(c+1)*512 + j*128 + t];
                }
            }
            #pragma unroll
            for (int f4l = 0; f4l < 4; f4l++) {
                int fb = f4l*4;
                float wa0 = S.u.s5.wa[(fb+0)*FF + t];
                float wa1 = S.u.s5.wa[(fb+1)*FF + t];
                float wa2 = S.u.s5.wa[(fb+2)*FF + t];
                float wa3 = S.u.s5.wa[(fb+3)*FF + t];
                float wf0 = S.u.s5.wf[(fb+0)*FF + t];
                float wf1 = S.u.s5.wf[(fb+1)*FF + t];
                float wf2 = S.u.s5.wf[(fb+2)*FF + t];
                float wf3 = S.u.s5.wf[(fb+3)*FF + t];
                unsigned long long wa01 = pk2(wa0, wa1), wa23 = pk2(wa2, wa3);
                unsigned long long wf01 = pk2(wf0, wf1), wf23 = pk2(wf2, wf3);
                int f4 = c*4 + f4l;
                #pragma unroll
                for (int i = 0; i < APB; i++) {
                    ulonglong2 y2 = ((const ulonglong2*)&S.y[i][0])[f4];
                    fma2(aA2[i], y2.x, wa01);
                    fma2(aA2[i], y2.y, wa23);
                    fma2(aF2[i], y2.x, wf01);
                    fma2(aF2[i], y2.y, wf23);
                }
            }
        }
        #pragma unroll
        for (int i = 0; i < APB; i++) {
            long gb = gaBase + i;
            float m = S.masky[i];
            float2 fa = upk2(aA2[i]);
            float2 ff = upk2(aF2[i]);
            g_att [gb*DD + t] = (fa.x + fa.y) * m;
            g_feat[gb*DD + t] = (ff.x + ff.y) * m;
        }
    }
    if (t < APB) g_masky[gaBase + t] = S.masky[t];
}

// ==========================================================================
// Kernel B: per-AA softmax pooling. 1 block per (b, aa), 128 threads = D.
// ==========================================================================
__global__ __launch_bounds__(128) void aa_kernel(
    const float* __restrict__ mask_aa,      // (B,NAA,1)
    const int*   __restrict__ seq_idx_atom, // (B,NA)
    const int*   __restrict__ seq_idx_aa,   // (B,NAA)
    const int*   __restrict__ aa_nb_idx)    // (B,NAA,14)
{
    const int t   = threadIdx.x;
    const long g2 = blockIdx.x;          // b*NAA + n
    const int b   = (int)(g2 >> 10);     // NAA = 1024

    __shared__ long  s_idx [KNC];
    __shared__ float s_gate[KNC];
    __shared__ float s_mnb [KNC];

    if (t < KNC) {
        int idx = aa_nb_idx[g2*KNC + t];
        long gi = (long)b*NA + idx;
        s_idx[t] = gi;
        int sn = seq_idx_atom[gi];
        int sa = seq_idx_aa[g2];
        s_gate[t] = (sn == sa) ? 1.f : 0.f;
        s_mnb[t]  = g_masky[gi];
    }
    __syncthreads();

    float l[KNC];
    float mx = -1e30f;
    #pragma unroll
    for (int j = 0; j < KNC; j++) {
        float v = (s_mnb[j] > 0.f) ? g_att[s_idx[j]*DD + t] : -1e9f;
        l[j] = v;
        mx = fmaxf(mx, v);
    }
    float E = 0.f;
    #pragma unroll
    for (int j = 0; j < KNC; j++) {
        l[j] = __expf(l[j] - mx);
        E += l[j];
    }
    float invE = 1.f / E;
    float wsum = 0.f;
    #pragma unroll
    for (int j = 0; j < KNC; j++) {
        float w = l[j] * invE * s_gate[j] * s_mnb[j];
        l[j] = w;
        wsum += w;
    }
    float p = 0.f;
    #pragma unroll
    for (int j = 0; j < KNC; j++)
        p += l[j] * g_feat[s_idx[j]*DD + t];
    p = p / (wsum + 1e-8f) * mask_aa[g2];
    g_pooled[g2*DD + t] = p;
}

// ==========================================================================
// Kernel C: per-channel masked mean/var over (B,NAA). 1 block per channel.
// ==========================================================================
__global__ __launch_bounds__(256) void stats_kernel(const float* __restrict__ mask_aa)
{
    const int d = blockIdx.x;
    const int t = threadIdx.x;
    float s1 = 0.f, s2 = 0.f, sm = 0.f;
    for (int r = t; r < BB*NAA; r += 256) {
        float m = mask_aa[r];
        float p = g_pooled[(long)r*DD + d];
        s1 += m*p; s2 += m*p*p; sm += m;
    }
    __shared__ float r1[256], r2[256], rm[256];
    r1[t] = s1; r2[t] = s2; rm[t] = sm;
    __syncthreads();
    for (int o = 128; o > 0; o >>= 1) {
        if (t < o) { r1[t] += r1[t+o]; r2[t] += r2[t+o]; rm[t] += rm[t+o]; }
        __syncthreads();
    }
    if (t == 0) {
        float n    = rm[0] + 1e-8f;
        float mean = r1[0] / n;
        float var  = (r2[0] - 2.f*mean*r1[0] + mean*mean*rm[0]) / n;
        g_mean[d]   = mean;
        g_invstd[d] = rsqrtf(var + 1e-5f);
    }
}

// ==========================================================================
// Kernel D: batchnorm affine + relu + write both outputs.
// ==========================================================================
__global__ __launch_bounds__(128) void final_kernel(
    const float* __restrict__ mask_aa,
    const float* __restrict__ bn_gamma,
    const float* __restrict__ bn_beta,
    float* __restrict__ out)
{
    const int t   = threadIdx.x;
    const long g2 = blockIdx.x;
    float m = mask_aa[g2];
    float p = g_pooled[g2*DD + t];
    float o = bn_gamma[t] * (p - g_mean[t]) * g_invstd[t] + bn_beta[t];
    o = fmaxf(o * m, 0.f);
    out[g2*DD + t] = o;
    if (t == 0) out[(long)BB*NAA*DD + g2] = m;   // second tuple element: mask_aa
}

// ==========================================================================
extern "C" void kernel_launch(void* const* d_in, const int* in_sizes, int n_in,
                              void* d_out, int out_size)
{
    const float* pc        = (const float*)d_in[0];
    const float* mask_atom = (const float*)d_in[1];
    const float* mask_aa   = (const float*)d_in[2];
    const float* attr      = (const float*)d_in[3];
    const float* gauss     = (const float*)d_in[4];
    const float* wnem      = (const float*)d_in[5];
    const float* watt      = (const float*)d_in[6];
    const float* wfeat     = (const float*)d_in[7];
    const float* gamma     = (const float*)d_in[8];
    const float* beta      = (const float*)d_in[9];
    const int*   fidx      = (const int*)d_in[10];
    const int*   aidx      = (const int*)d_in[11];
    const int*   nbidx     = (const int*)d_in[12];
    const int*   seqa      = (const int*)d_in[13];
    const int*   seqaa     = (const int*)d_in[14];
    const int*   aanb      = (const int*)d_in[15];
    float* out = (float*)d_out;

    atom_kernel<<<BB*NA/APB, 128>>>(pc, mask_atom, attr, gauss, wnem, watt, wfeat,
                                    fidx, aidx, nbidx);
    aa_kernel<<<BB*NAA, 128>>>(mask_aa, seqa, seqaa, aanb);
    stats_kernel<<<DD, 256>>>(mask_aa);
    final_kernel<<<BB*NAA, 128>>>(mask_aa, gamma, beta, out);
}

// round 8
// speedup vs baseline: 1.3127x; 1.3127x over previous
#include <cuda_runtime.h>
#include <math.h>

#define BB   8
#define NA   4096
#define NAA  1024
#define NPC  4096
#define KNB  16
#define KNC  14
#define GG   32
#define DA   12
#define FF   128
#define DD   128
#define NATTR 39     // NCAT+1
#define APB  8       // atoms per block in atom_kernel
#define GP   33      // padded inner dim of sh_g (bank spread)

// -------- scratch (static device globals; no allocation allowed) ----------
__device__ float g_M     [BB*NA*GG*DA]; // 50.3 MB  (M matrix, K=384)
__device__ float g_y     [BB*NA*FF];    // 16.8 MB
__device__ float g_att   [BB*NA*DD];    // 16 MB
__device__ float g_feat  [BB*NA*DD];    // 16 MB
__device__ float g_masky [BB*NA];       // 128 KB
__device__ float g_pooled[BB*NAA*DD];   // 4 MB
__device__ float g_mean  [DD];
__device__ float g_invstd[DD];

// -------- packed f32x2 helpers (SASS FFMA2 path) --------------------------
__device__ __forceinline__ unsigned long long pk2(float lo, float hi) {
    unsigned long long r;
    asm("mov.b64 %0, {%1, %2};" : "=l"(r) : "f"(lo), "f"(hi));
    return r;
}
__device__ __forceinline__ void fma2(unsigned long long& d,
                                     unsigned long long a,
                                     unsigned long long b) {
    asm("fma.rn.f32x2 %0, %1, %2, %0;" : "+l"(d) : "l"(a), "l"(b));
}
__device__ __forceinline__ float2 upk2(unsigned long long v) {
    float2 f;
    asm("mov.b64 {%0, %1}, %2;" : "=f"(f.x), "=f"(f.y) : "l"(v));
    return f;
}

// ==========================================================================
// Kernel A: per-atom stages 0-3. 8 atoms per block, 128 threads.
// Writes M (atoms x 384) to gmem; GEMMs handled by gemm_kernel.
// ==========================================================================
__global__ __launch_bounds__(128) void atom_kernel(
    const float* __restrict__ pc,         // (B,NPC,3)
    const float* __restrict__ mask_atom,  // (B,NA,1)
    const float* __restrict__ attr_table, // (39,12)
    const float* __restrict__ gauss,      // (32,3)
    const int*   __restrict__ frame_idx,  // (B,NA,3)
    const int*   __restrict__ attr_idx,   // (B,NA)
    const int*   __restrict__ nb_idx)     // (B,NA,16)
{
    __shared__ float sh_attr [NATTR*DA];
    __shared__ float sh_mattr[NATTR];
    __shared__ float sh_gc   [GG*3];
    __shared__ float sh_R    [APB][9];
    __shared__ float sh_c    [APB][3];
    __shared__ float sh_masky[APB];
    __shared__ __align__(16) float sh_g   [APB][KNB][GP];
    __shared__ __align__(16) float sh_anb [APB][KNB][DA];

    const int t  = threadIdx.x;
    const int ai = t >> 4;
    const int k  = t & 15;
    const long gaBase = (long)blockIdx.x * APB;
    const long ga = gaBase + ai;               // global atom id
    const int  b  = (int)(ga >> 12);           // NA = 4096

    // ---- stage 0: stage small tables in smem ----
    for (int i = t; i < NATTR*DA; i += 128) sh_attr[i] = attr_table[i];
    for (int i = t; i < GG*3;     i += 128) sh_gc[i]   = gauss[i];
    __syncthreads();

    // ---- stage 1: mattr per table row; frame R per atom ----
    if (t < NATTR) {
        float any = 0.f;
        #pragma unroll
        for (int a = 0; a < DA; a++) if (sh_attr[t*DA + a] != 0.f) any = 1.f;
        sh_mattr[t] = any;
    }
    if (k == 0) {
        const int* fi = frame_idx + ga*3;
        const float* pb = pc + (long)b*NPC*3;
        int i0 = fi[0], i1 = fi[1], i2 = fi[2];
        float c0 = pb[i1*3+0], c1 = pb[i1*3+1], c2 = pb[i1*3+2];
        float a0 = pb[i2*3+0]-c0, a1 = pb[i2*3+1]-c1, a2 = pb[i2*3+2]-c2;
        float n1 = sqrtf(a0*a0 + a1*a1 + a2*a2);
        float s1 = 1.f / (n1 + 1e-8f);
        float u10 = a0*s1, u11 = a1*s1, u12 = a2*s1;
        float v0 = pb[i0*3+0]-c0, v1 = pb[i0*3+1]-c1, v2 = pb[i0*3+2]-c2;
        float dp = v0*u10 + v1*u11 + v2*u12;
        float w0 = v0 - dp*u10, w1 = v1 - dp*u11, w2 = v2 - dp*u12;
        float n2 = sqrtf(w0*w0 + w1*w1 + w2*w2);
        float s2 = 1.f / (n2 + 1e-8f);
        float u20 = w0*s2, u21 = w1*s2, u22 = w2*s2;
        float u30 = u11*u22 - u12*u21;
        float u31 = u12*u20 - u10*u22;
        float u32 = u10*u21 - u11*u20;
        sh_R[ai][0]=u10; sh_R[ai][1]=u11; sh_R[ai][2]=u12;
        sh_R[ai][3]=u20; sh_R[ai][4]=u21; sh_R[ai][5]=u22;
        sh_R[ai][6]=u30; sh_R[ai][7]=u31; sh_R[ai][8]=u32;
        sh_c[ai][0]=c0;  sh_c[ai][1]=c1;  sh_c[ai][2]=c2;
    }
    __syncthreads();

    // ---- stage 2: per-(atom, neighbor): gaussian features + attr gather ----
    if (k == 0) {
        int own = attr_idx[ga];
        sh_masky[ai] = mask_atom[ga] * sh_mattr[own];
    }
    {
        int nb  = nb_idx[ga*KNB + k];             // [0, NA)
        long nbg = (long)b*NA + nb;
        int fi1 = frame_idx[nbg*3 + 1];
        const float* pb = pc + (long)b*NPC*3;
        float dx = pb[fi1*3+0] - sh_c[ai][0];
        float dy = pb[fi1*3+1] - sh_c[ai][1];
        float dz = pb[fi1*3+2] - sh_c[ai][2];
        float r0 = sh_R[ai][0]*dx + sh_R[ai][1]*dy + sh_R[ai][2]*dz;
        float r1 = sh_R[ai][3]*dx + sh_R[ai][4]*dy + sh_R[ai][5]*dz;
        float r2 = sh_R[ai][6]*dx + sh_R[ai][7]*dy + sh_R[ai][8]*dz;
        #pragma unroll
        for (int gi = 0; gi < GG; gi++) {
            float gx = r0 - sh_gc[gi*3+0];
            float gy = r1 - sh_gc[gi*3+1];
            float gz = r2 - sh_gc[gi*3+2];
            sh_g[ai][k][gi] = __expf(-0.5f * (gx*gx + gy*gy + gz*gz));
        }
        int na = attr_idx[nbg];
        float m = sh_mattr[na];
        #pragma unroll
        for (int a = 0; a < DA; a++)
            sh_anb[ai][k][a] = sh_attr[na*DA + a] * m;
    }
    __syncthreads();

    // ---- stage 3: M[atom][gi*12+a] = sum_k g * a_nb -> gmem ----
    for (int q = t; q < APB*GG*(DA/4); q += 128) {
        int a2 = q / (GG*(DA/4));
        int r  = q - a2*(GG*(DA/4));
        int gi = r / (DA/4);
        int aq = r - gi*(DA/4);
        unsigned long long acc01 = 0ull, acc23 = 0ull;
        const ulonglong2* anb2 = (const ulonglong2*)&sh_anb[a2][0][0];
        #pragma unroll
        for (int kk = 0; kk < KNB; kk++) {
            float gv = sh_g[a2][kk][gi];
            unsigned long long gg = pk2(gv, gv);
            ulonglong2 av = anb2[kk*(DA/4) + aq];
            fma2(acc01, av.x, gg);
            fma2(acc23, av.y, gg);
        }
        float2 r01 = upk2(acc01), r23 = upk2(acc23);
        ((float4*)g_M)[((gaBase + a2)*(GG*DA) >> 2) + gi*(DA/4) + aq] =
            make_float4(r01.x, r01.y, r23.x, r23.y);
    }
    if (t < APB) g_masky[gaBase + t] = sh_masky[t];
}

// ==========================================================================
// Generic tiled GEMM over device-global A/C, selected by mode:
//   mode 0: C=g_y    = (g_M @ W)/16 * masky   (K=384)
//   mode 1: C=g_att  = (g_y @ W)    * masky   (K=128)
//   mode 2: C=g_feat = (g_y @ W)    * masky   (K=128)
// BM=128 rows/block, BN=128, BK=32. 256 threads, 8x8 microtile, FFMA2.
// ==========================================================================
__global__ __launch_bounds__(256, 2) void gemm_kernel(
    const float* __restrict__ W, int mode)
{
    __shared__ __align__(16) float As[32][132];  // [kk][row]
    __shared__ __align__(16) float Ws[32][128];  // [kk][f]
    const int t  = threadIdx.x;
    const int tx = t & 15;         // f microtile: f = tx*8..+7
    const int ty = t >> 4;         // row microtile: row = ty*8..+7
    const long rowBase = (long)blockIdx.x * 128;

    const float* A = (mode == 0) ? g_M : g_y;
    float*       C = (mode == 0) ? g_y : (mode == 1 ? g_att : g_feat);
    const int  K_dim = (mode == 0) ? (GG*DA) : FF;
    const float smul = (mode == 0) ? (1.f/(float)KNB) : 1.f;

    unsigned long long acc[8][4];
    #pragma unroll
    for (int i = 0; i < 8; i++)
        #pragma unroll
        for (int p = 0; p < 4; p++) acc[i][p] = 0ull;

    const int nchunk = K_dim >> 5;
    for (int kc = 0; kc < nchunk; kc++) {
        // load A tile: 128 rows x 32 k = 1024 float4
        #pragma unroll
        for (int j = 0; j < 4; j++) {
            int fid  = j*256 + t;
            int row  = fid >> 3;
            int k4   = fid & 7;
            float4 v = *(const float4*)&A[(rowBase + row)*K_dim + kc*32 + k4*4];
            As[k4*4+0][row] = v.x;
            As[k4*4+1][row] = v.y;
            As[k4*4+2][row] = v.z;
            As[k4*4+3][row] = v.w;
        }
        // load W tile: 32 k x 128 f = 1024 float4
        #pragma unroll
        for (int j = 0; j < 4; j++) {
            int fid = j*256 + t;
            int kk  = fid >> 5;
            int f4  = fid & 31;
            *(float4*)&Ws[kk][f4*4] =
                *(const float4*)&W[(kc*32 + kk)*FF + f4*4];
        }
        __syncthreads();

        #pragma unroll
        for (int kk = 0; kk < 32; kk++) {
            ulonglong2 b01 = *(const ulonglong2*)&Ws[kk][tx*8];
            ulonglong2 b23 = *(const ulonglong2*)&Ws[kk][tx*8+4];
            float4 a0 = *(const float4*)&As[kk][ty*8];
            float4 a1 = *(const float4*)&As[kk][ty*8+4];
            unsigned long long s;
            s = pk2(a0.x, a0.x);
            fma2(acc[0][0], b01.x, s); fma2(acc[0][1], b01.y, s);
            fma2(acc[0][2], b23.x, s); fma2(acc[0][3], b23.y, s);
            s = pk2(a0.y, a0.y);
            fma2(acc[1][0], b01.x, s); fma2(acc[1][1], b01.y, s);
            fma2(acc[1][2], b23.x, s); fma2(acc[1][3], b23.y, s);
            s = pk2(a0.z, a0.z);
            fma2(acc[2][0], b01.x, s); fma2(acc[2][1], b01.y, s);
            fma2(acc[2][2], b23.x, s); fma2(acc[2][3], b23.y, s);
            s = pk2(a0.w, a0.w);
            fma2(acc[3][0], b01.x, s); fma2(acc[3][1], b01.y, s);
            fma2(acc[3][2], b23.x, s); fma2(acc[3][3], b23.y, s);
            s = pk2(a1.x, a1.x);
            fma2(acc[4][0], b01.x, s); fma2(acc[4][1], b01.y, s);
            fma2(acc[4][2], b23.x, s); fma2(acc[4][3], b23.y, s);
            s = pk2(a1.y, a1.y);
            fma2(acc[5][0], b01.x, s); fma2(acc[5][1], b01.y, s);
            fma2(acc[5][2], b23.x, s); fma2(acc[5][3], b23.y, s);
            s = pk2(a1.z, a1.z);
            fma2(acc[6][0], b01.x, s); fma2(acc[6][1], b01.y, s);
            fma2(acc[6][2], b23.x, s); fma2(acc[6][3], b23.y, s);
            s = pk2(a1.w, a1.w);
            fma2(acc[7][0], b01.x, s); fma2(acc[7][1], b01.y, s);
            fma2(acc[7][2], b23.x, s); fma2(acc[7][3], b23.y, s);
        }
        __syncthreads();
    }

    // epilogue: scale by masky*smul, store 8 rows x 8 f
    #pragma unroll
    for (int i = 0; i < 8; i++) {
        long row = rowBase + ty*8 + i;
        float sc = g_masky[row] * smul;
        float2 v0 = upk2(acc[i][0]);
        float2 v1 = upk2(acc[i][1]);
        float2 v2 = upk2(acc[i][2]);
        float2 v3 = upk2(acc[i][3]);
        float* cp = C + row*FF + tx*8;
        *(float4*)cp       = make_float4(v0.x*sc, v0.y*sc, v1.x*sc, v1.y*sc);
        *(float4*)(cp + 4) = make_float4(v2.x*sc, v2.y*sc, v3.x*sc, v3.y*sc);
    }
}

// ==========================================================================
// Kernel B: per-AA softmax pooling. 1 block per (b, aa), 128 threads = D.
// ==========================================================================
__global__ __launch_bounds__(128) void aa_kernel(
    const float* __restrict__ mask_aa,      // (B,NAA,1)
    const int*   __restrict__ seq_idx_atom, // (B,NA)
    const int*   __restrict__ seq_idx_aa,   // (B,NAA)
    const int*   __restrict__ aa_nb_idx)    // (B,NAA,14)
{
    const int t   = threadIdx.x;
    const long g2 = blockIdx.x;          // b*NAA + n
    const int b   = (int)(g2 >> 10);     // NAA = 1024

    __shared__ long  s_idx [KNC];
    __shared__ float s_gate[KNC];
    __shared__ float s_mnb [KNC];

    if (t < KNC) {
        int idx = aa_nb_idx[g2*KNC + t];
        long gi = (long)b*NA + idx;
        s_idx[t] = gi;
        int sn = seq_idx_atom[gi];
        int sa = seq_idx_aa[g2];
        s_gate[t] = (sn == sa) ? 1.f : 0.f;
        s_mnb[t]  = g_masky[gi];
    }
    __syncthreads();

    float l[KNC];
    float mx = -1e30f;
    #pragma unroll
    for (int j = 0; j < KNC; j++) {
        float v = (s_mnb[j] > 0.f) ? g_att[s_idx[j]*DD + t] : -1e9f;
        l[j] = v;
        mx = fmaxf(mx, v);
    }
    float E = 0.f;
    #pragma unroll
    for (int j = 0; j < KNC; j++) {
        l[j] = __expf(l[j] - mx);
        E += l[j];
    }
    float invE = 1.f / E;
    float wsum = 0.f;
    #pragma unroll
    for (int j = 0; j < KNC; j++) {
        float w = l[j] * invE * s_gate[j] * s_mnb[j];
        l[j] = w;
        wsum += w;
    }
    float p = 0.f;
    #pragma unroll
    for (int j = 0; j < KNC; j++)
        p += l[j] * g_feat[s_idx[j]*DD + t];
    p = p / (wsum + 1e-8f) * mask_aa[g2];
    g_pooled[g2*DD + t] = p;
}

// ==========================================================================
// Kernel C: per-channel masked mean/var over (B,NAA). 1 block per channel.
// ==========================================================================
__global__ __launch_bounds__(256) void stats_kernel(const float* __restrict__ mask_aa)
{
    const int d = blockIdx.x;
    const int t = threadIdx.x;
    float s1 = 0.f, s2 = 0.f, sm = 0.f;
    for (int r = t; r < BB*NAA; r += 256) {
        float m = mask_aa[r];
        float p = g_pooled[(long)r*DD + d];
        s1 += m*p; s2 += m*p*p; sm += m;
    }
    __shared__ float r1[256], r2[256], rm[256];
    r1[t] = s1; r2[t] = s2; rm[t] = sm;
    __syncthreads();
    for (int o = 128; o > 0; o >>= 1) {
        if (t < o) { r1[t] += r1[t+o]; r2[t] += r2[t+o]; rm[t] += rm[t+o]; }
        __syncthreads();
    }
    if (t == 0) {
        float n    = rm[0] + 1e-8f;
        float mean = r1[0] / n;
        float var  = (r2[0] - 2.f*mean*r1[0] + mean*mean*rm[0]) / n;
        g_mean[d]   = mean;
        g_invstd[d] = rsqrtf(var + 1e-5f);
    }
}

// ==========================================================================
// Kernel D: batchnorm affine + relu + write both outputs.
// ==========================================================================
__global__ __launch_bounds__(128) void final_kernel(
    const float* __restrict__ mask_aa,
    const float* __restrict__ bn_gamma,
    const float* __restrict__ bn_beta,
    float* __restrict__ out)
{
    const int t   = threadIdx.x;
    const long g2 = blockIdx.x;
    float m = mask_aa[g2];
    float p = g_pooled[g2*DD + t];
    float o = bn_gamma[t] * (p - g_mean[t]) * g_invstd[t] + bn_beta[t];
    o = fmaxf(o * m, 0.f);
    out[g2*DD + t] = o;
    if (t == 0) out[(long)BB*NAA*DD + g2] = m;   // second tuple element: mask_aa
}

// ==========================================================================
extern "C" void kernel_launch(void* const* d_in, const int* in_sizes, int n_in,
                              void* d_out, int out_size)
{
    const float* pc        = (const float*)d_in[0];
    const float* mask_atom = (const float*)d_in[1];
    const float* mask_aa   = (const float*)d_in[2];
    const float* attr      = (const float*)d_in[3];
    const float* gauss     = (const float*)d_in[4];
    const float* wnem      = (const float*)d_in[5];
    const float* watt      = (const float*)d_in[6];
    const float* wfeat     = (const float*)d_in[7];
    const float* gamma     = (const float*)d_in[8];
    const float* beta      = (const float*)d_in[9];
    const int*   fidx      = (const int*)d_in[10];
    const int*   aidx      = (const int*)d_in[11];
    const int*   nbidx     = (const int*)d_in[12];
    const int*   seqa      = (const int*)d_in[13];
    const int*   seqaa     = (const int*)d_in[14];
    const int*   aanb      = (const int*)d_in[15];
    float* out = (float*)d_out;

    atom_kernel<<<BB*NA/APB, 128>>>(pc, mask_atom, attr, gauss,
                                    fidx, aidx, nbidx);
    gemm_kernel<<<BB*NA/128, 256>>>(wnem, 0);
    gemm_kernel<<<BB*NA/128, 256>>>(watt, 1);
    gemm_kernel<<<BB*NA/128, 256>>>(wfeat, 2);
    aa_kernel<<<BB*NAA, 128>>>(mask_aa, seqa, seqaa, aanb);
    stats_kernel<<<DD, 256>>>(mask_aa);
    final_kernel<<<BB*NAA, 128>>>(mask_aa, gamma, beta, out);
}